// round 13
// baseline (speedup 1.0000x reference)
#include <cuda_runtime.h>
#include <cuda_fp16.h>
#include <cuda_bf16.h>
#include <cstdint>

// Problem constants (match reference)
#define NNODES 10000
#define BATCH  8
#define INSZ   64
#define UNITS  64
#define NMAT   3
#define ROWW   (INSZ * BATCH)      // 512 elems per node-row
#define ROWU4  64                  // uint4 (8 halfs) per fp16 node-row
#define MAXDEG 96                  // bucket capacity per row (mean deg ~33)
#define NM     (NNODES * BATCH)    // 80000 GEMM rows

// ---------------- scratch (device globals; no allocation allowed) -----------
__device__ __half g_x0h[NNODES * ROWW];
__device__ __half g_x1h[NNODES * ROWW];
__device__ __half g_x2h[NNODES * ROWW];
__device__ __half g_wh[NMAT * INSZ * UNITS];    // W fp16, k' = m*64+i, [192][64]
__device__ int2   g_bucket[NNODES * MAXDEG];    // (col, float_bits(val))
__device__ int    g_cursor[NNODES];

// ---------------- prep0: zero cursors + W fp16 reindex -----------------------
__global__ void prep0_kernel(const float* __restrict__ W) {
    int idx = blockIdx.x * blockDim.x + threadIdx.x;
    if (idx < NNODES) g_cursor[idx] = 0;
    if (idx < NMAT * INSZ * UNITS) {
        int kp = idx >> 6;          // m*64+i
        int u  = idx & 63;
        int m  = kp >> 6;
        int i  = kp & 63;
        g_wh[idx] = __float2half(W[(i * NMAT + m) * UNITS + u]);
    }
}

// ---------------- fused transpose + scatter ----------------------------------
// blocks [0, 5000): transpose in[b][n][i] -> x0h[(n*8+b)][i] (fp16)
// blocks [5000, ...): bucket scatter, 4 edges per thread
#define T_BLOCKS 5000
__global__ void __launch_bounds__(256) prep1_kernel(
        const float* __restrict__ in,
        const int* __restrict__ rows, const int* __restrict__ cols,
        const float* __restrict__ vals, int nnz) {
    const int bid = blockIdx.x;
    const int tid = threadIdx.x;
    if (bid < T_BLOCKS) {
        int f = bid * 256 + tid;      // float4 index over NM*16 = 1.28M
        int M  = f >> 4;              // n*8+b
        int i4 = f & 15;
        int n = M >> 3, b = M & 7;
        float4 v = ((const float4*)in)[(size_t)b * (NNODES * 16) + n * 16 + i4];
        __half2 h0 = __floats2half2_rn(v.x, v.y);
        __half2 h1 = __floats2half2_rn(v.z, v.w);
        uint2 hv;
        hv.x = *reinterpret_cast<unsigned*>(&h0);
        hv.y = *reinterpret_cast<unsigned*>(&h1);
        ((uint2*)g_x0h)[f] = hv;
    } else {
        int base = (bid - T_BLOCKS) * 1024 + tid * 4;
        if (base + 3 < nnz) {
            int4   r4 = *(const int4*)(rows + base);
            int4   c4 = *(const int4*)(cols + base);
            float4 v4 = *(const float4*)(vals + base);
            int p0 = atomicAdd(&g_cursor[r4.x], 1);
            int p1 = atomicAdd(&g_cursor[r4.y], 1);
            int p2 = atomicAdd(&g_cursor[r4.z], 1);
            int p3 = atomicAdd(&g_cursor[r4.w], 1);
            if (p0 < MAXDEG) g_bucket[r4.x * MAXDEG + p0] = make_int2(c4.x, __float_as_int(v4.x));
            if (p1 < MAXDEG) g_bucket[r4.y * MAXDEG + p1] = make_int2(c4.y, __float_as_int(v4.y));
            if (p2 < MAXDEG) g_bucket[r4.z * MAXDEG + p2] = make_int2(c4.z, __float_as_int(v4.z));
            if (p3 < MAXDEG) g_bucket[r4.w * MAXDEG + p3] = make_int2(c4.w, __float_as_int(v4.w));
        } else {
#pragma unroll
            for (int k = 0; k < 4; ++k) {
                int e = base + k;
                if (e < nnz) {
                    int r = rows[e];
                    int pos = atomicAdd(&g_cursor[r], 1);
                    if (pos < MAXDEG)
                        g_bucket[r * MAXDEG + pos] = make_int2(cols[e], __float_as_int(vals[e]));
                }
            }
        }
    }
}

// ---------------- SpMM: warp per row, pipelined fp16 gathers -----------------
struct Acc16 { float2 v[8]; };

__device__ __forceinline__ void gather_fma(Acc16& a, float v, uint4 q0, uint4 q1) {
    const unsigned* u = &q0.x;
#pragma unroll
    for (int k = 0; k < 4; ++k) {
        float2 f = __half22float2(*reinterpret_cast<const __half2*>(&u[k]));
        a.v[k].x += v * f.x; a.v[k].y += v * f.y;
    }
    const unsigned* w = &q1.x;
#pragma unroll
    for (int k = 0; k < 4; ++k) {
        float2 f = __half22float2(*reinterpret_cast<const __half2*>(&w[k]));
        a.v[4 + k].x += v * f.x; a.v[4 + k].y += v * f.y;
    }
}

__device__ __forceinline__ Acc16 spmm_row(int n, int lane, const __half* __restrict__ xh) {
    const int cv = g_cursor[n];
    const int cnt = cv < MAXDEG ? cv : MAXDEG;
    const int2* __restrict__ eb = g_bucket + n * MAXDEG;
    const uint4* __restrict__ x16 = (const uint4*)xh;
    Acc16 acc;
#pragma unroll
    for (int k = 0; k < 8; ++k) acc.v[k] = make_float2(0.f, 0.f);

    int e = 0;
    if (cnt >= 4) {
        // software pipeline: edge records for iter k+1 loaded before iter k's FMA
        int4 p0 = *(const int4*)(eb);
        int4 p1 = *(const int4*)(eb + 2);
        while (true) {
            const int4 c0 = p0, c1 = p1;
            const uint4* r0 = x16 + (size_t)c0.x * ROWU4 + 2 * lane;
            const uint4* r1 = x16 + (size_t)c0.z * ROWU4 + 2 * lane;
            const uint4* r2 = x16 + (size_t)c1.x * ROWU4 + 2 * lane;
            const uint4* r3 = x16 + (size_t)c1.z * ROWU4 + 2 * lane;
            uint4 a0 = r0[0], a1 = r0[1];
            uint4 b0 = r1[0], b1 = r1[1];
            uint4 g0 = r2[0], g1 = r2[1];
            uint4 d0 = r3[0], d1 = r3[1];
            e += 4;
            const bool more = (e + 3 < cnt);
            if (more) { p0 = *(const int4*)(eb + e); p1 = *(const int4*)(eb + e + 2); }
            gather_fma(acc, __int_as_float(c0.y), a0, a1);
            gather_fma(acc, __int_as_float(c0.w), b0, b1);
            gather_fma(acc, __int_as_float(c1.y), g0, g1);
            gather_fma(acc, __int_as_float(c1.w), d0, d1);
            if (!more) break;
        }
    }
    for (; e < cnt; ++e) {
        int2 p = eb[e];
        const uint4* r0 = x16 + (size_t)p.x * ROWU4 + 2 * lane;
        uint4 a0 = r0[0], a1 = r0[1];
        gather_fma(acc, __int_as_float(p.y), a0, a1);
    }
    return acc;
}

__device__ __forceinline__ void store_row_h(__half* dsth, int n, int lane, const Acc16& a) {
    uint4 h[2];
    unsigned* hu = &h[0].x;
#pragma unroll
    for (int k = 0; k < 8; ++k) {
        __half2 t = __floats2half2_rn(a.v[k].x, a.v[k].y);
        hu[k] = *reinterpret_cast<unsigned*>(&t);
    }
    uint4* dh = (uint4*)(dsth + (size_t)n * ROWW) + 2 * lane;
    dh[0] = h[0]; dh[1] = h[1];
}

__global__ void __launch_bounds__(256) spmm1_kernel() {
    const int wid = (blockIdx.x * blockDim.x + threadIdx.x) >> 5;
    if (wid >= NNODES) return;
    const int lane = threadIdx.x & 31;
    Acc16 acc = spmm_row(wid, lane, g_x0h);
    store_row_h(g_x1h, wid, lane, acc);
}

// x2 = 2 * L x1 - x0   (x0 read from fp16 copy)
__global__ void __launch_bounds__(256) spmm2_kernel() {
    const int wid = (blockIdx.x * blockDim.x + threadIdx.x) >> 5;
    if (wid >= NNODES) return;
    const int lane = threadIdx.x & 31;
    Acc16 acc = spmm_row(wid, lane, g_x1h);
    const uint4* x0r = (const uint4*)g_x0h + (size_t)wid * ROWU4 + 2 * lane;
    uint4 q0 = x0r[0], q1 = x0r[1];
    const unsigned* qu = &q0.x;
#pragma unroll
    for (int k = 0; k < 4; ++k) {
        float2 f = __half22float2(*reinterpret_cast<const __half2*>(&qu[k]));
        acc.v[k].x = 2.f * acc.v[k].x - f.x;
        acc.v[k].y = 2.f * acc.v[k].y - f.y;
    }
    const unsigned* qw = &q1.x;
#pragma unroll
    for (int k = 0; k < 4; ++k) {
        float2 f = __half22float2(*reinterpret_cast<const __half2*>(&qw[k]));
        acc.v[4 + k].x = 2.f * acc.v[4 + k].x - f.x;
        acc.v[4 + k].y = 2.f * acc.v[4 + k].y - f.y;
    }
    store_row_h(g_x2h, wid, lane, acc);
}

// ---------------- tensor-core GEMM ------------------------------------------
// out[M=80000, 64] = sum_m Xm[M, 64] @ Wm[64, 64] + bias,  M = n*8+b
// Block: 128 threads (4 warps), M-tile 32, N 64, K 192.
// Grid-stride over 4 tiles per block: B (24.6KB) loaded ONCE per block.
#define GM_M 32
#define GM_NTILES (NM / GM_M)      // 2500
#define GM_GRID 625                // 4 tiles per block
#define A_STRIDE 200   // halfs; 400B, 16B-phase shift per row
#define B_STRIDE 72    // halfs; 144B

__device__ __forceinline__ void ldsm_x4(unsigned* r, uint32_t addr) {
    asm volatile("ldmatrix.sync.aligned.m8n8.x4.shared.b16 {%0,%1,%2,%3}, [%4];"
        : "=r"(r[0]), "=r"(r[1]), "=r"(r[2]), "=r"(r[3]) : "r"(addr));
}
__device__ __forceinline__ void ldsm_x4_t(unsigned* r, uint32_t addr) {
    asm volatile("ldmatrix.sync.aligned.m8n8.x4.trans.shared.b16 {%0,%1,%2,%3}, [%4];"
        : "=r"(r[0]), "=r"(r[1]), "=r"(r[2]), "=r"(r[3]) : "r"(addr));
}
__device__ __forceinline__ void mma16816(float* c, const unsigned* a, const unsigned* b) {
    asm volatile(
        "mma.sync.aligned.m16n8k16.row.col.f32.f16.f16.f32 "
        "{%0,%1,%2,%3}, {%4,%5,%6,%7}, {%8,%9}, {%0,%1,%2,%3};"
        : "+f"(c[0]), "+f"(c[1]), "+f"(c[2]), "+f"(c[3])
        : "r"(a[0]), "r"(a[1]), "r"(a[2]), "r"(a[3]), "r"(b[0]), "r"(b[1]));
}

__global__ void __launch_bounds__(128) mma_gemm_kernel(const float* __restrict__ bias,
                                                       float* __restrict__ out) {
    __shared__ __half As[GM_M * A_STRIDE];
    __shared__ __half Bs[NMAT * INSZ * B_STRIDE];
    __shared__ float  bs[UNITS];
    const int t = threadIdx.x;

    // Load B once: 192 rows x 64 halfs
    for (int idx = t; idx < 192 * 8; idx += 128) {
        int kk = idx >> 3, s8 = idx & 7;
        uint4 v = ((const uint4*)g_wh)[kk * 8 + s8];
        *(uint4*)&Bs[kk * B_STRIDE + s8 * 8] = v;
    }
    if (t < UNITS) bs[t] = bias[t];

    const int lane = t & 31, w = t >> 5;
    const int mrow = (w & 1) * 16;
    const int ncol = (w >> 1) * 32;
    const uint32_t a_smem = (uint32_t)__cvta_generic_to_shared(As);
    const uint32_t b_smem = (uint32_t)__cvta_generic_to_shared(Bs);

    for (int tile = blockIdx.x; tile < GM_NTILES; tile += GM_GRID) {
        const size_t Mbase = (size_t)tile * GM_M;
        __syncthreads();   // protect As from previous iteration readers (also orders B on iter 0)
        for (int idx = t; idx < GM_M * 24; idx += 128) {
            int row = idx / 24, seg = idx % 24;
            int mat = seg >> 3, s8 = seg & 7;
            size_t g = (Mbase + row) * 8 + s8;
            uint4 v;
            if (mat == 0)      v = ((const uint4*)g_x0h)[g];
            else if (mat == 1) v = ((const uint4*)g_x1h)[g];
            else               v = ((const uint4*)g_x2h)[g];
            *(uint4*)&As[row * A_STRIDE + mat * 64 + s8 * 8] = v;
        }
        __syncthreads();

        float acc[4][4];
#pragma unroll
        for (int i = 0; i < 4; ++i)
#pragma unroll
            for (int j = 0; j < 4; ++j) acc[i][j] = 0.f;

#pragma unroll
        for (int ks = 0; ks < 12; ++ks) {
            unsigned a[4];
            uint32_t aaddr = a_smem +
                (((mrow + (lane & 15)) * A_STRIDE) + ks * 16 + (lane >> 4) * 8) * 2;
            ldsm_x4(a, aaddr);
#pragma unroll
            for (int t16 = 0; t16 < 2; ++t16) {
                unsigned b[4];
                uint32_t baddr = b_smem +
                    (((ks * 16 + (lane & 15)) * B_STRIDE) + ncol + t16 * 16 + (lane >> 4) * 8) * 2;
                ldsm_x4_t(b, baddr);
                mma16816(acc[2 * t16],     a, b);
                mma16816(acc[2 * t16 + 1], a, b + 2);
            }
        }

        // Store: rows M = Mbase + mrow + g (+8); out[b][n][u], n = M>>3, b = M&7
        const int g = lane >> 2, q = lane & 3;
        const size_t M0 = Mbase + mrow + g;
        const size_t M1 = M0 + 8;
        const size_t o0 = (size_t)(M0 & 7) * (NNODES * UNITS) + (M0 >> 3) * UNITS;
        const size_t o1 = (size_t)(M1 & 7) * (NNODES * UNITS) + (M1 >> 3) * UNITS;
#pragma unroll
        for (int t8 = 0; t8 < 4; ++t8) {
            int u = ncol + t8 * 8 + q * 2;
            float bi0 = bs[u], bi1 = bs[u + 1];
            *(float2*)&out[o0 + u] = make_float2(acc[t8][0] + bi0, acc[t8][1] + bi1);
            *(float2*)&out[o1 + u] = make_float2(acc[t8][2] + bi0, acc[t8][3] + bi1);
        }
    }
}

// ---------------- launch -----------------------------------------------------
extern "C" void kernel_launch(void* const* d_in, const int* in_sizes, int n_in,
                              void* d_out, int out_size) {
    const float* inputs = (const float*)d_in[0];
    const int*   rows   = (const int*)d_in[1];
    const int*   cols   = (const int*)d_in[2];
    const float* vals   = (const float*)d_in[3];
    const float* weights = (const float*)d_in[4];
    const float* biases  = (const float*)d_in[5];
    float* out = (float*)d_out;
    const int nnz = in_sizes[1];

    // zero cursors + W prep
    prep0_kernel<<<(NMAT * INSZ * UNITS + 255) / 256, 256>>>(weights);
    // fused transpose + bucket scatter
    const int s_blocks = (nnz + 1023) / 1024;
    prep1_kernel<<<T_BLOCKS + s_blocks, 256>>>(inputs, rows, cols, vals, nnz);
    // Chebyshev diffusion (warp per row, pipelined fp16 gathers)
    spmm1_kernel<<<(NNODES * 32 + 255) / 256, 256>>>();
    spmm2_kernel<<<(NNODES * 32 + 255) / 256, 256>>>();
    // Output projection (tensor cores)
    mma_gemm_kernel<<<GM_GRID, 128>>>(biases, out);
}

// round 14
// speedup vs baseline: 1.0840x; 1.0840x over previous
#include <cuda_runtime.h>
#include <cuda_fp16.h>
#include <cuda_bf16.h>
#include <cstdint>

// Problem constants (match reference)
#define NNODES 10000
#define BATCH  8
#define INSZ   64
#define UNITS  64
#define NMAT   3
#define ROWW   (INSZ * BATCH)      // 512 elems per node-row
#define ROWU4  64                  // uint4 (8 halfs) per fp16 node-row
#define MAXDEG 96                  // bucket capacity per row (mean deg ~33)
#define NM     (NNODES * BATCH)    // 80000 GEMM rows

// ---------------- scratch (device globals; no allocation allowed) -----------
__device__ __half g_x0h[NNODES * ROWW];
__device__ __half g_x1h[NNODES * ROWW];
__device__ __half g_x2h[NNODES * ROWW];
__device__ __half g_wh[NMAT * INSZ * UNITS];    // W fp16, k' = m*64+i, [192][64]
__device__ int2   g_bucket[NNODES * MAXDEG];    // (col, float_bits(val))
__device__ int    g_cursor[NNODES];

// ---------------- prep0: zero cursors + W fp16 reindex -----------------------
__global__ void prep0_kernel(const float* __restrict__ W) {
    int idx = blockIdx.x * blockDim.x + threadIdx.x;
    if (idx < NNODES) g_cursor[idx] = 0;
    if (idx < NMAT * INSZ * UNITS) {
        int kp = idx >> 6;          // m*64+i
        int u  = idx & 63;
        int m  = kp >> 6;
        int i  = kp & 63;
        g_wh[idx] = __float2half(W[(i * NMAT + m) * UNITS + u]);
    }
}

// ---------------- fused transpose + scatter ----------------------------------
// blocks [0, 5000): transpose in[b][n][i] -> x0h[(n*8+b)][i] (fp16)
// blocks [5000, ...): bucket scatter, 4 edges per thread
#define T_BLOCKS 5000
__global__ void __launch_bounds__(256) prep1_kernel(
        const float* __restrict__ in,
        const int* __restrict__ rows, const int* __restrict__ cols,
        const float* __restrict__ vals, int nnz) {
    const int bid = blockIdx.x;
    const int tid = threadIdx.x;
    if (bid < T_BLOCKS) {
        int f = bid * 256 + tid;      // float4 index over NM*16 = 1.28M
        int M  = f >> 4;              // n*8+b
        int i4 = f & 15;
        int n = M >> 3, b = M & 7;
        float4 v = ((const float4*)in)[(size_t)b * (NNODES * 16) + n * 16 + i4];
        __half2 h0 = __floats2half2_rn(v.x, v.y);
        __half2 h1 = __floats2half2_rn(v.z, v.w);
        uint2 hv;
        hv.x = *reinterpret_cast<unsigned*>(&h0);
        hv.y = *reinterpret_cast<unsigned*>(&h1);
        ((uint2*)g_x0h)[f] = hv;
    } else {
        int base = (bid - T_BLOCKS) * 1024 + tid * 4;
        if (base + 3 < nnz) {
            int4   r4 = *(const int4*)(rows + base);
            int4   c4 = *(const int4*)(cols + base);
            float4 v4 = *(const float4*)(vals + base);
            int p0 = atomicAdd(&g_cursor[r4.x], 1);
            int p1 = atomicAdd(&g_cursor[r4.y], 1);
            int p2 = atomicAdd(&g_cursor[r4.z], 1);
            int p3 = atomicAdd(&g_cursor[r4.w], 1);
            if (p0 < MAXDEG) g_bucket[r4.x * MAXDEG + p0] = make_int2(c4.x, __float_as_int(v4.x));
            if (p1 < MAXDEG) g_bucket[r4.y * MAXDEG + p1] = make_int2(c4.y, __float_as_int(v4.y));
            if (p2 < MAXDEG) g_bucket[r4.z * MAXDEG + p2] = make_int2(c4.z, __float_as_int(v4.z));
            if (p3 < MAXDEG) g_bucket[r4.w * MAXDEG + p3] = make_int2(c4.w, __float_as_int(v4.w));
        } else {
#pragma unroll
            for (int k = 0; k < 4; ++k) {
                int e = base + k;
                if (e < nnz) {
                    int r = rows[e];
                    int pos = atomicAdd(&g_cursor[r], 1);
                    if (pos < MAXDEG)
                        g_bucket[r * MAXDEG + pos] = make_int2(cols[e], __float_as_int(vals[e]));
                }
            }
        }
    }
}

// ---------------- SpMM: HALF-row per warp (2 warps per node row) -------------
// Warp covers uint4 index off = half*32 + lane (8 halfs = 16B per edge).
struct Acc8 { float2 v[4]; };

__device__ __forceinline__ void fma8(Acc8& a, float v, uint4 q) {
    const unsigned* u = &q.x;
#pragma unroll
    for (int k = 0; k < 4; ++k) {
        float2 f = __half22float2(*reinterpret_cast<const __half2*>(&u[k]));
        a.v[k].x += v * f.x; a.v[k].y += v * f.y;
    }
}

__device__ __forceinline__ Acc8 spmm_half_row(int n, int off, const __half* __restrict__ xh) {
    const int cv = g_cursor[n];
    const int cnt = cv < MAXDEG ? cv : MAXDEG;
    const int2* __restrict__ eb = g_bucket + n * MAXDEG;
    const uint4* __restrict__ x16 = (const uint4*)xh;
    Acc8 acc;
#pragma unroll
    for (int k = 0; k < 4; ++k) acc.v[k] = make_float2(0.f, 0.f);

    int e = 0;
    for (; e + 3 < cnt; e += 4) {
        int4 p0 = *(const int4*)(eb + e);       // edges e, e+1
        int4 p1 = *(const int4*)(eb + e + 2);   // edges e+2, e+3
        uint4 qa = x16[(size_t)p0.x * ROWU4 + off];
        uint4 qb = x16[(size_t)p0.z * ROWU4 + off];
        uint4 qc = x16[(size_t)p1.x * ROWU4 + off];
        uint4 qd = x16[(size_t)p1.z * ROWU4 + off];
        fma8(acc, __int_as_float(p0.y), qa);
        fma8(acc, __int_as_float(p0.w), qb);
        fma8(acc, __int_as_float(p1.y), qc);
        fma8(acc, __int_as_float(p1.w), qd);
    }
    for (; e < cnt; ++e) {
        int2 p = eb[e];
        uint4 qa = x16[(size_t)p.x * ROWU4 + off];
        fma8(acc, __int_as_float(p.y), qa);
    }
    return acc;
}

__device__ __forceinline__ uint4 pack8(const Acc8& a) {
    uint4 h;
    unsigned* hu = &h.x;
#pragma unroll
    for (int k = 0; k < 4; ++k) {
        __half2 t = __floats2half2_rn(a.v[k].x, a.v[k].y);
        hu[k] = *reinterpret_cast<unsigned*>(&t);
    }
    return h;
}

__global__ void __launch_bounds__(128) spmm1_kernel() {
    const int gw = (blockIdx.x * blockDim.x + threadIdx.x) >> 5;   // global warp
    if (gw >= NNODES * 2) return;
    const int n = gw >> 1;
    const int off = (gw & 1) * 32 + (threadIdx.x & 31);
    Acc8 acc = spmm_half_row(n, off, g_x0h);
    ((uint4*)g_x1h)[(size_t)n * ROWU4 + off] = pack8(acc);
}

// x2 = 2 * L x1 - x0   (x0 read from fp16 copy)
__global__ void __launch_bounds__(128) spmm2_kernel() {
    const int gw = (blockIdx.x * blockDim.x + threadIdx.x) >> 5;
    if (gw >= NNODES * 2) return;
    const int n = gw >> 1;
    const int off = (gw & 1) * 32 + (threadIdx.x & 31);
    Acc8 acc = spmm_half_row(n, off, g_x1h);
    uint4 q0 = ((const uint4*)g_x0h)[(size_t)n * ROWU4 + off];
    const unsigned* qu = &q0.x;
#pragma unroll
    for (int k = 0; k < 4; ++k) {
        float2 f = __half22float2(*reinterpret_cast<const __half2*>(&qu[k]));
        acc.v[k].x = 2.f * acc.v[k].x - f.x;
        acc.v[k].y = 2.f * acc.v[k].y - f.y;
    }
    ((uint4*)g_x2h)[(size_t)n * ROWU4 + off] = pack8(acc);
}

// ---------------- tensor-core GEMM ------------------------------------------
// out[M=80000, 64] = sum_m Xm[M, 64] @ Wm[64, 64] + bias,  M = n*8+b
// Block: 128 threads (4 warps), M-tile 32, N 64, K 192.
// Grid-stride over 4 tiles per block: B (24.6KB) loaded ONCE per block.
#define GM_M 32
#define GM_NTILES (NM / GM_M)      // 2500
#define GM_GRID 625                // 4 tiles per block
#define A_STRIDE 200   // halfs; 400B, 16B-phase shift per row
#define B_STRIDE 72    // halfs; 144B

__device__ __forceinline__ void ldsm_x4(unsigned* r, uint32_t addr) {
    asm volatile("ldmatrix.sync.aligned.m8n8.x4.shared.b16 {%0,%1,%2,%3}, [%4];"
        : "=r"(r[0]), "=r"(r[1]), "=r"(r[2]), "=r"(r[3]) : "r"(addr));
}
__device__ __forceinline__ void ldsm_x4_t(unsigned* r, uint32_t addr) {
    asm volatile("ldmatrix.sync.aligned.m8n8.x4.trans.shared.b16 {%0,%1,%2,%3}, [%4];"
        : "=r"(r[0]), "=r"(r[1]), "=r"(r[2]), "=r"(r[3]) : "r"(addr));
}
__device__ __forceinline__ void mma16816(float* c, const unsigned* a, const unsigned* b) {
    asm volatile(
        "mma.sync.aligned.m16n8k16.row.col.f32.f16.f16.f32 "
        "{%0,%1,%2,%3}, {%4,%5,%6,%7}, {%8,%9}, {%0,%1,%2,%3};"
        : "+f"(c[0]), "+f"(c[1]), "+f"(c[2]), "+f"(c[3])
        : "r"(a[0]), "r"(a[1]), "r"(a[2]), "r"(a[3]), "r"(b[0]), "r"(b[1]));
}

__global__ void __launch_bounds__(128) mma_gemm_kernel(const float* __restrict__ bias,
                                                       float* __restrict__ out) {
    __shared__ __half As[GM_M * A_STRIDE];
    __shared__ __half Bs[NMAT * INSZ * B_STRIDE];
    __shared__ float  bs[UNITS];
    const int t = threadIdx.x;

    // Load B once: 192 rows x 64 halfs
    for (int idx = t; idx < 192 * 8; idx += 128) {
        int kk = idx >> 3, s8 = idx & 7;
        uint4 v = ((const uint4*)g_wh)[kk * 8 + s8];
        *(uint4*)&Bs[kk * B_STRIDE + s8 * 8] = v;
    }
    if (t < UNITS) bs[t] = bias[t];

    const int lane = t & 31, w = t >> 5;
    const int mrow = (w & 1) * 16;
    const int ncol = (w >> 1) * 32;
    const uint32_t a_smem = (uint32_t)__cvta_generic_to_shared(As);
    const uint32_t b_smem = (uint32_t)__cvta_generic_to_shared(Bs);

    for (int tile = blockIdx.x; tile < GM_NTILES; tile += GM_GRID) {
        const size_t Mbase = (size_t)tile * GM_M;
        __syncthreads();   // protect As from previous iteration readers (also orders B on iter 0)
        for (int idx = t; idx < GM_M * 24; idx += 128) {
            int row = idx / 24, seg = idx % 24;
            int mat = seg >> 3, s8 = seg & 7;
            size_t g = (Mbase + row) * 8 + s8;
            uint4 v;
            if (mat == 0)      v = ((const uint4*)g_x0h)[g];
            else if (mat == 1) v = ((const uint4*)g_x1h)[g];
            else               v = ((const uint4*)g_x2h)[g];
            *(uint4*)&As[row * A_STRIDE + mat * 64 + s8 * 8] = v;
        }
        __syncthreads();

        float acc[4][4];
#pragma unroll
        for (int i = 0; i < 4; ++i)
#pragma unroll
            for (int j = 0; j < 4; ++j) acc[i][j] = 0.f;

#pragma unroll
        for (int ks = 0; ks < 12; ++ks) {
            unsigned a[4];
            uint32_t aaddr = a_smem +
                (((mrow + (lane & 15)) * A_STRIDE) + ks * 16 + (lane >> 4) * 8) * 2;
            ldsm_x4(a, aaddr);
#pragma unroll
            for (int t16 = 0; t16 < 2; ++t16) {
                unsigned b[4];
                uint32_t baddr = b_smem +
                    (((ks * 16 + (lane & 15)) * B_STRIDE) + ncol + t16 * 16 + (lane >> 4) * 8) * 2;
                ldsm_x4_t(b, baddr);
                mma16816(acc[2 * t16],     a, b);
                mma16816(acc[2 * t16 + 1], a, b + 2);
            }
        }

        // Store: rows M = Mbase + mrow + g (+8); out[b][n][u], n = M>>3, b = M&7
        const int g = lane >> 2, q = lane & 3;
        const size_t M0 = Mbase + mrow + g;
        const size_t M1 = M0 + 8;
        const size_t o0 = (size_t)(M0 & 7) * (NNODES * UNITS) + (M0 >> 3) * UNITS;
        const size_t o1 = (size_t)(M1 & 7) * (NNODES * UNITS) + (M1 >> 3) * UNITS;
#pragma unroll
        for (int t8 = 0; t8 < 4; ++t8) {
            int u = ncol + t8 * 8 + q * 2;
            float bi0 = bs[u], bi1 = bs[u + 1];
            *(float2*)&out[o0 + u] = make_float2(acc[t8][0] + bi0, acc[t8][1] + bi1);
            *(float2*)&out[o1 + u] = make_float2(acc[t8][2] + bi0, acc[t8][3] + bi1);
        }
    }
}

// ---------------- launch -----------------------------------------------------
extern "C" void kernel_launch(void* const* d_in, const int* in_sizes, int n_in,
                              void* d_out, int out_size) {
    const float* inputs = (const float*)d_in[0];
    const int*   rows   = (const int*)d_in[1];
    const int*   cols   = (const int*)d_in[2];
    const float* vals   = (const float*)d_in[3];
    const float* weights = (const float*)d_in[4];
    const float* biases  = (const float*)d_in[5];
    float* out = (float*)d_out;
    const int nnz = in_sizes[1];

    // zero cursors + W prep
    prep0_kernel<<<(NMAT * INSZ * UNITS + 255) / 256, 256>>>(weights);
    // fused transpose + bucket scatter
    const int s_blocks = (nnz + 1023) / 1024;
    prep1_kernel<<<T_BLOCKS + s_blocks, 256>>>(inputs, rows, cols, vals, nnz);
    // Chebyshev diffusion (half-row per warp, fp16 gathers)
    spmm1_kernel<<<(NNODES * 2 * 32 + 127) / 128, 128>>>();
    spmm2_kernel<<<(NNODES * 2 * 32 + 127) / 128, 128>>>();
    // Output projection (tensor cores)
    mma_gemm_kernel<<<GM_GRID, 128>>>(biases, out);
}

// round 15
// speedup vs baseline: 1.2571x; 1.1598x over previous
#include <cuda_runtime.h>
#include <cuda_fp16.h>
#include <cuda_bf16.h>
#include <cstdint>

// Problem constants (match reference)
#define NNODES 10000
#define BATCH  8
#define INSZ   64
#define UNITS  64
#define NMAT   3
#define ROWW   (INSZ * BATCH)      // 512 elems per node-row
#define ROWU4  64                  // uint4 (8 halfs) per fp16 node-row
#define MAXDEG 96                  // bucket capacity per row (mean deg ~33)
#define NM     (NNODES * BATCH)    // 80000 GEMM rows

// ---------------- scratch (device globals; no allocation allowed) -----------
// g_cursor is zero-initialized at module load; every launch re-zeroes it at
// the END (gemm tail), so the "cursors are 0 on entry" invariant holds for
// the correctness run and for every graph replay.
__device__ __half g_x0h[NNODES * ROWW];
__device__ __half g_x1h[NNODES * ROWW];
__device__ __half g_x2h[NNODES * ROWW];
__device__ __half g_wh[NMAT * INSZ * UNITS];    // W fp16, k' = m*64+i, [192][64]
__device__ int2   g_bucket[NNODES * MAXDEG];    // (col, float_bits(val))
__device__ int    g_cursor[NNODES];

// ---------------- fused transpose + scatter + W prep -------------------------
// blocks [0, 5000): transpose in[b][n][i] -> x0h[(n*8+b)][i] (fp16)
// blocks [5000, 5000+s_blocks): bucket scatter, 4 edges per thread
// blocks [5000+s_blocks, +48): W fp16 reindex
#define T_BLOCKS 5000
#define W_BLOCKS 48
__global__ void __launch_bounds__(256) prep_kernel(
        const float* __restrict__ in,
        const int* __restrict__ rows, const int* __restrict__ cols,
        const float* __restrict__ vals, int nnz, int s_blocks,
        const float* __restrict__ W) {
    const int bid = blockIdx.x;
    const int tid = threadIdx.x;
    if (bid < T_BLOCKS) {
        int f = bid * 256 + tid;      // float4 index over NM*16 = 1.28M
        int M  = f >> 4;              // n*8+b
        int i4 = f & 15;
        int n = M >> 3, b = M & 7;
        float4 v = ((const float4*)in)[(size_t)b * (NNODES * 16) + n * 16 + i4];
        __half2 h0 = __floats2half2_rn(v.x, v.y);
        __half2 h1 = __floats2half2_rn(v.z, v.w);
        uint2 hv;
        hv.x = *reinterpret_cast<unsigned*>(&h0);
        hv.y = *reinterpret_cast<unsigned*>(&h1);
        ((uint2*)g_x0h)[f] = hv;
    } else if (bid < T_BLOCKS + s_blocks) {
        int base = (bid - T_BLOCKS) * 1024 + tid * 4;
        if (base + 3 < nnz) {
            int4   r4 = *(const int4*)(rows + base);
            int4   c4 = *(const int4*)(cols + base);
            float4 v4 = *(const float4*)(vals + base);
            int p0 = atomicAdd(&g_cursor[r4.x], 1);
            int p1 = atomicAdd(&g_cursor[r4.y], 1);
            int p2 = atomicAdd(&g_cursor[r4.z], 1);
            int p3 = atomicAdd(&g_cursor[r4.w], 1);
            if (p0 < MAXDEG) g_bucket[r4.x * MAXDEG + p0] = make_int2(c4.x, __float_as_int(v4.x));
            if (p1 < MAXDEG) g_bucket[r4.y * MAXDEG + p1] = make_int2(c4.y, __float_as_int(v4.y));
            if (p2 < MAXDEG) g_bucket[r4.z * MAXDEG + p2] = make_int2(c4.z, __float_as_int(v4.z));
            if (p3 < MAXDEG) g_bucket[r4.w * MAXDEG + p3] = make_int2(c4.w, __float_as_int(v4.w));
        } else {
#pragma unroll
            for (int k = 0; k < 4; ++k) {
                int e = base + k;
                if (e < nnz) {
                    int r = rows[e];
                    int pos = atomicAdd(&g_cursor[r], 1);
                    if (pos < MAXDEG)
                        g_bucket[r * MAXDEG + pos] = make_int2(cols[e], __float_as_int(vals[e]));
                }
            }
        }
    } else {
        int idx = (bid - T_BLOCKS - s_blocks) * 256 + tid;
        if (idx < NMAT * INSZ * UNITS) {
            int kp = idx >> 6;          // m*64+i
            int u  = idx & 63;
            int m  = kp >> 6;
            int i  = kp & 63;
            g_wh[idx] = __float2half(W[(i * NMAT + m) * UNITS + u]);
        }
    }
}

// ---------------- SpMM: HALF-row per warp (2 warps per node row) -------------
// Warp covers uint4 index off = half*32 + lane (8 halfs = 16B per edge).
struct Acc8 { float2 v[4]; };

__device__ __forceinline__ void fma8(Acc8& a, float v, uint4 q) {
    const unsigned* u = &q.x;
#pragma unroll
    for (int k = 0; k < 4; ++k) {
        float2 f = __half22float2(*reinterpret_cast<const __half2*>(&u[k]));
        a.v[k].x += v * f.x; a.v[k].y += v * f.y;
    }
}

__device__ __forceinline__ Acc8 spmm_half_row(int n, int off, const __half* __restrict__ xh) {
    const int cv = g_cursor[n];
    const int cnt = cv < MAXDEG ? cv : MAXDEG;
    const int2* __restrict__ eb = g_bucket + n * MAXDEG;
    const uint4* __restrict__ x16 = (const uint4*)xh;
    Acc8 acc;
#pragma unroll
    for (int k = 0; k < 4; ++k) acc.v[k] = make_float2(0.f, 0.f);

    int e = 0;
    for (; e + 3 < cnt; e += 4) {
        int4 p0 = *(const int4*)(eb + e);       // edges e, e+1
        int4 p1 = *(const int4*)(eb + e + 2);   // edges e+2, e+3
        uint4 qa = x16[(size_t)p0.x * ROWU4 + off];
        uint4 qb = x16[(size_t)p0.z * ROWU4 + off];
        uint4 qc = x16[(size_t)p1.x * ROWU4 + off];
        uint4 qd = x16[(size_t)p1.z * ROWU4 + off];
        fma8(acc, __int_as_float(p0.y), qa);
        fma8(acc, __int_as_float(p0.w), qb);
        fma8(acc, __int_as_float(p1.y), qc);
        fma8(acc, __int_as_float(p1.w), qd);
    }
    for (; e < cnt; ++e) {
        int2 p = eb[e];
        uint4 qa = x16[(size_t)p.x * ROWU4 + off];
        fma8(acc, __int_as_float(p.y), qa);
    }
    return acc;
}

__device__ __forceinline__ uint4 pack8(const Acc8& a) {
    uint4 h;
    unsigned* hu = &h.x;
#pragma unroll
    for (int k = 0; k < 4; ++k) {
        __half2 t = __floats2half2_rn(a.v[k].x, a.v[k].y);
        hu[k] = *reinterpret_cast<unsigned*>(&t);
    }
    return h;
}

__global__ void __launch_bounds__(128) spmm1_kernel() {
    const int gw = (blockIdx.x * blockDim.x + threadIdx.x) >> 5;   // global warp
    if (gw >= NNODES * 2) return;
    const int n = gw >> 1;
    const int off = (gw & 1) * 32 + (threadIdx.x & 31);
    Acc8 acc = spmm_half_row(n, off, g_x0h);
    ((uint4*)g_x1h)[(size_t)n * ROWU4 + off] = pack8(acc);
}

// x2 = 2 * L x1 - x0   (x0 read from fp16 copy)
__global__ void __launch_bounds__(128) spmm2_kernel() {
    const int gw = (blockIdx.x * blockDim.x + threadIdx.x) >> 5;
    if (gw >= NNODES * 2) return;
    const int n = gw >> 1;
    const int off = (gw & 1) * 32 + (threadIdx.x & 31);
    Acc8 acc = spmm_half_row(n, off, g_x1h);
    uint4 q0 = ((const uint4*)g_x0h)[(size_t)n * ROWU4 + off];
    const unsigned* qu = &q0.x;
#pragma unroll
    for (int k = 0; k < 4; ++k) {
        float2 f = __half22float2(*reinterpret_cast<const __half2*>(&qu[k]));
        acc.v[k].x = 2.f * acc.v[k].x - f.x;
        acc.v[k].y = 2.f * acc.v[k].y - f.y;
    }
    ((uint4*)g_x2h)[(size_t)n * ROWU4 + off] = pack8(acc);
}

// ---------------- tensor-core GEMM (register-prefetch double buffer) --------
// out[M=80000, 64] = sum_m Xm[M, 64] @ Wm[64, 64] + bias,  M = n*8+b
// Block: 128 threads (4 warps), M-tile 32, N 64, K 192.
// Grid-stride over 4 tiles; next tile's A prefetched to regs during mma.
// Tail: zero g_cursor for the next launch/replay.
#define GM_M 32
#define GM_NTILES (NM / GM_M)      // 2500
#define GM_GRID 625                // 4 tiles per block
#define A_STRIDE 200   // halfs; 400B, 16B-phase shift per row
#define B_STRIDE 72    // halfs; 144B

__device__ __forceinline__ void ldsm_x4(unsigned* r, uint32_t addr) {
    asm volatile("ldmatrix.sync.aligned.m8n8.x4.shared.b16 {%0,%1,%2,%3}, [%4];"
        : "=r"(r[0]), "=r"(r[1]), "=r"(r[2]), "=r"(r[3]) : "r"(addr));
}
__device__ __forceinline__ void ldsm_x4_t(unsigned* r, uint32_t addr) {
    asm volatile("ldmatrix.sync.aligned.m8n8.x4.trans.shared.b16 {%0,%1,%2,%3}, [%4];"
        : "=r"(r[0]), "=r"(r[1]), "=r"(r[2]), "=r"(r[3]) : "r"(addr));
}
__device__ __forceinline__ void mma16816(float* c, const unsigned* a, const unsigned* b) {
    asm volatile(
        "mma.sync.aligned.m16n8k16.row.col.f32.f16.f16.f32 "
        "{%0,%1,%2,%3}, {%4,%5,%6,%7}, {%8,%9}, {%0,%1,%2,%3};"
        : "+f"(c[0]), "+f"(c[1]), "+f"(c[2]), "+f"(c[3])
        : "r"(a[0]), "r"(a[1]), "r"(a[2]), "r"(a[3]), "r"(b[0]), "r"(b[1]));
}

__global__ void __launch_bounds__(128) mma_gemm_kernel(const float* __restrict__ bias,
                                                       float* __restrict__ out) {
    __shared__ __half As[GM_M * A_STRIDE];
    __shared__ __half Bs[NMAT * INSZ * B_STRIDE];
    __shared__ float  bs[UNITS];
    const int t = threadIdx.x;

    // Load B once: 192 rows x 64 halfs
    for (int idx = t; idx < 192 * 8; idx += 128) {
        int kk = idx >> 3, s8 = idx & 7;
        uint4 v = ((const uint4*)g_wh)[kk * 8 + s8];
        *(uint4*)&Bs[kk * B_STRIDE + s8 * 8] = v;
    }
    if (t < UNITS) bs[t] = bias[t];

    const int lane = t & 31, w = t >> 5;
    const int mrow = (w & 1) * 16;
    const int ncol = (w >> 1) * 32;
    const uint32_t a_smem = (uint32_t)__cvta_generic_to_shared(As);
    const uint32_t b_smem = (uint32_t)__cvta_generic_to_shared(Bs);

    // A prefetch: 6 segments per thread (32 rows x 24 seg = 768 = 128 x 6)
    uint4 pref[6];
    int prow[6], pseg[6];
#pragma unroll
    for (int s = 0; s < 6; ++s) {
        int idx = s * 128 + t;
        prow[s] = idx / 24;
        pseg[s] = idx % 24;
    }
    auto load_tile = [&](int tile) {
        const size_t Mbase = (size_t)tile * GM_M;
#pragma unroll
        for (int s = 0; s < 6; ++s) {
            int mat = pseg[s] >> 3, s8 = pseg[s] & 7;
            size_t g = (Mbase + prow[s]) * 8 + s8;
            if (mat == 0)      pref[s] = ((const uint4*)g_x0h)[g];
            else if (mat == 1) pref[s] = ((const uint4*)g_x1h)[g];
            else               pref[s] = ((const uint4*)g_x2h)[g];
        }
    };

    load_tile(blockIdx.x);

    for (int tile = blockIdx.x; tile < GM_NTILES; tile += GM_GRID) {
        // commit prefetched A to smem
#pragma unroll
        for (int s = 0; s < 6; ++s) {
            int mat = pseg[s] >> 3, s8 = pseg[s] & 7;
            *(uint4*)&As[prow[s] * A_STRIDE + mat * 64 + s8 * 8] = pref[s];
        }
        __syncthreads();   // As (and Bs/bs on iter 0) visible to all

        // issue next tile's loads; latency overlaps the mma below
        if (tile + GM_GRID < GM_NTILES) load_tile(tile + GM_GRID);

        float acc[4][4];
#pragma unroll
        for (int i = 0; i < 4; ++i)
#pragma unroll
            for (int j = 0; j < 4; ++j) acc[i][j] = 0.f;

#pragma unroll
        for (int ks = 0; ks < 12; ++ks) {
            unsigned a[4];
            uint32_t aaddr = a_smem +
                (((mrow + (lane & 15)) * A_STRIDE) + ks * 16 + (lane >> 4) * 8) * 2;
            ldsm_x4(a, aaddr);
#pragma unroll
            for (int t16 = 0; t16 < 2; ++t16) {
                unsigned b[4];
                uint32_t baddr = b_smem +
                    (((ks * 16 + (lane & 15)) * B_STRIDE) + ncol + t16 * 16 + (lane >> 4) * 8) * 2;
                ldsm_x4_t(b, baddr);
                mma16816(acc[2 * t16],     a, b);
                mma16816(acc[2 * t16 + 1], a, b + 2);
            }
        }

        // Store: rows M = Mbase + mrow + g (+8); out[b][n][u], n = M>>3, b = M&7
        const size_t Mbase = (size_t)tile * GM_M;
        const int g = lane >> 2, q = lane & 3;
        const size_t M0 = Mbase + mrow + g;
        const size_t M1 = M0 + 8;
        const size_t o0 = (size_t)(M0 & 7) * (NNODES * UNITS) + (M0 >> 3) * UNITS;
        const size_t o1 = (size_t)(M1 & 7) * (NNODES * UNITS) + (M1 >> 3) * UNITS;
#pragma unroll
        for (int t8 = 0; t8 < 4; ++t8) {
            int u = ncol + t8 * 8 + q * 2;
            float bi0 = bs[u], bi1 = bs[u + 1];
            *(float2*)&out[o0 + u] = make_float2(acc[t8][0] + bi0, acc[t8][1] + bi1);
            *(float2*)&out[o1 + u] = make_float2(acc[t8][2] + bi0, acc[t8][3] + bi1);
        }
        __syncthreads();   // all warps done reading As before next commit
    }

    // zero cursors for the next launch / graph replay
    int ci = blockIdx.x * 128 + t;
    if (ci < NNODES) g_cursor[ci] = 0;
}

// ---------------- launch -----------------------------------------------------
extern "C" void kernel_launch(void* const* d_in, const int* in_sizes, int n_in,
                              void* d_out, int out_size) {
    const float* inputs = (const float*)d_in[0];
    const int*   rows   = (const int*)d_in[1];
    const int*   cols   = (const int*)d_in[2];
    const float* vals   = (const float*)d_in[3];
    const float* weights = (const float*)d_in[4];
    const float* biases  = (const float*)d_in[5];
    float* out = (float*)d_out;
    const int nnz = in_sizes[1];

    // fused transpose + bucket scatter + W prep (cursors zeroed by prior gemm)
    const int s_blocks = (nnz + 1023) / 1024;
    prep_kernel<<<T_BLOCKS + s_blocks + W_BLOCKS, 256>>>(inputs, rows, cols, vals,
                                                         nnz, s_blocks, weights);
    // Chebyshev diffusion (half-row per warp, fp16 gathers)
    spmm1_kernel<<<(NNODES * 2 * 32 + 127) / 128, 128>>>();
    spmm2_kernel<<<(NNODES * 2 * 32 + 127) / 128, 128>>>();
    // Output projection (tensor cores) + cursor re-zero
    mma_gemm_kernel<<<GM_GRID, 128>>>(biases, out);
}